// round 8
// baseline (speedup 1.0000x reference)
#include <cuda_runtime.h>
#include <cstdint>

#define HID 128
#define MAXN 50000
#define MAXE 640000

// ---------------- scratch ----------------
__device__ __align__(256) float g_z[MAXN * HID];
__device__ __align__(256) float g_agg[MAXN * HID];
__device__ __align__(256) float g_t[MAXN * HID];
__device__ __align__(256) float g_stats[8 * 2 * HID];
__device__ int g_cnt[MAXN];
__device__ int g_cur[MAXN];
__device__ int g_rowptr[MAXN + 1];
__device__ int g_elist[MAXE];

// ---------------- helpers ----------------
__device__ __forceinline__ float tf32_rna(float x) {
    unsigned o;
    asm("cvt.rna.tf32.f32 %0, %1;" : "=r"(o) : "f"(x));
    return __uint_as_float(o);
}
__device__ __forceinline__ void mma_tf32(float& d0, float& d1, float& d2, float& d3,
                                         unsigned a0, unsigned a1, unsigned a2, unsigned a3,
                                         unsigned b0, unsigned b1) {
    asm("mma.sync.aligned.m16n8k8.row.col.f32.tf32.tf32.f32 "
        "{%0,%1,%2,%3}, {%4,%5,%6,%7}, {%8,%9}, {%0,%1,%2,%3};"
        : "+f"(d0), "+f"(d1), "+f"(d2), "+f"(d3)
        : "r"(a0), "r"(a1), "r"(a2), "r"(a3), "r"(b0), "r"(b1));
}

// ================= CSR build =================
__global__ void hist_kernel(const int* __restrict__ dst, int E) {
    int i = blockIdx.x * blockDim.x + threadIdx.x;
    if (i < E) atomicAdd(&g_cnt[dst[i]], 1);
}

__global__ void __launch_bounds__(1024) scan_kernel(int N, int E) {
    __shared__ int part[1024];
    int tid = threadIdx.x;
    int chunk = (N + 1023) / 1024;
    int base = tid * chunk;
    int s = 0;
    for (int j = 0; j < chunk; j++) {
        int idx = base + j;
        if (idx < N) s += g_cnt[idx];
    }
    part[tid] = s;
    __syncthreads();
    for (int off = 1; off < 1024; off <<= 1) {
        int v = (tid >= off) ? part[tid - off] : 0;
        __syncthreads();
        part[tid] += v;
        __syncthreads();
    }
    int run = (tid == 0) ? 0 : part[tid - 1];
    for (int j = 0; j < chunk; j++) {
        int idx = base + j;
        if (idx < N) {
            g_rowptr[idx] = run;
            run += g_cnt[idx];
            g_cnt[idx] = 0;
            g_cur[idx] = 0;
        }
    }
    if (tid == 1023) g_rowptr[N] = E;
    g_stats[tid] = 0.f;
    g_stats[tid + 1024] = 0.f;
}

__global__ void scatter_kernel(const int* __restrict__ dst, int E) {
    int i = blockIdx.x * blockDim.x + threadIdx.x;
    if (i < E) {
        int d = dst[i];
        int p = atomicAdd(&g_cur[d], 1);
        g_elist[g_rowptr[d] + p] = i;
    }
}

// ================= aggregate: warp per node (DRAM roofline) =================
template <bool BN>
__global__ void __launch_bounds__(256) agg_kernel(
    const float* __restrict__ z, const float* __restrict__ ea,
    const int* __restrict__ srcI, const float* __restrict__ stat_in,
    const float* __restrict__ gamma, const float* __restrict__ beta,
    float* __restrict__ agg, int N, float invN) {
    __shared__ float s_sc[HID], s_sh[HID];
    if (BN) {
        if (threadIdx.x < HID) {
            int c = threadIdx.x;
            float mu = stat_in[c] * invN;
            float var = stat_in[HID + c] * invN - mu * mu;
            float sv = gamma[c] * rsqrtf(var + 1e-5f);
            s_sc[c] = sv;
            s_sh[c] = beta[c] - sv * mu;
        }
        __syncthreads();
    }
    int warp = (blockIdx.x * blockDim.x + threadIdx.x) >> 5;
    int lane = threadIdx.x & 31;
    if (warp >= N) return;

    float4 sc, sh;
    if (BN) {
        sc = *(const float4*)&s_sc[lane * 4];
        sh = *(const float4*)&s_sh[lane * 4];
    }

    int idx = g_rowptr[warp];
    const int end = g_rowptr[warp + 1];
    float4 acc = make_float4(0.f, 0.f, 0.f, 0.f);

#define EDGE_BODY(E_, S_)                                                     \
    {                                                                         \
        float4 zv = __ldg((const float4*)(z + (size_t)(S_) * HID) + lane);    \
        float4 av = __ldcs((const float4*)(ea + (size_t)(E_) * HID) + lane);  \
        if (BN) {                                                             \
            zv.x = fmaf(sc.x, zv.x, sh.x); zv.y = fmaf(sc.y, zv.y, sh.y);     \
            zv.z = fmaf(sc.z, zv.z, sh.z); zv.w = fmaf(sc.w, zv.w, sh.w);     \
        }                                                                     \
        acc.x += fmaxf(zv.x + av.x, 0.f);                                     \
        acc.y += fmaxf(zv.y + av.y, 0.f);                                     \
        acc.z += fmaxf(zv.z + av.z, 0.f);                                     \
        acc.w += fmaxf(zv.w + av.w, 0.f);                                     \
    }

    for (; idx + 4 <= end; idx += 4) {
        int e0 = __ldg(g_elist + idx);
        int e1 = __ldg(g_elist + idx + 1);
        int e2 = __ldg(g_elist + idx + 2);
        int e3 = __ldg(g_elist + idx + 3);
        int s0 = __ldg(srcI + e0);
        int s1 = __ldg(srcI + e1);
        int s2 = __ldg(srcI + e2);
        int s3 = __ldg(srcI + e3);
        EDGE_BODY(e0, s0) EDGE_BODY(e1, s1) EDGE_BODY(e2, s2) EDGE_BODY(e3, s3)
    }
    for (; idx < end; idx++) {
        int e0 = __ldg(g_elist + idx);
        int s0 = __ldg(srcI + e0);
        EDGE_BODY(e0, s0)
    }
#undef EDGE_BODY
    ((float4*)(agg + (size_t)warp * HID))[lane] = acc;
}

// ================= tf32 tensor GEMM (3xTF32), BM=64, BN=128, K in 2 halves ==========
// smem floats: As_hi[64*68] As_lo[64*68] Ws_hi[64*136] Ws_lo[64*136] sc,sh[128] stat[256]
#define AP 68
#define WP 136
static const int SM_AH = 0;
static const int SM_AL = SM_AH + 64 * AP;
static const int SM_WH = SM_AL + 64 * AP;
static const int SM_WL = SM_WH + 64 * WP;
static const int SM_SC = SM_WL + 64 * WP;
static const int SM_SH = SM_SC + HID;
static const int SM_ST = SM_SH + HID;
static const int GEMM_SMEM = (SM_ST + 256) * 4;  // 106496 B

template <bool BN_IN, bool HAS_A2, bool RELU_IN, bool RELU_OUT, bool STATS>
__global__ void __launch_bounds__(256, 2) gemm_kernel(
    const float* __restrict__ A, const float* __restrict__ A2,
    const float* __restrict__ stat_in, const float* __restrict__ gamma,
    const float* __restrict__ beta, float invN,
    const float* __restrict__ W, const float* __restrict__ bias,
    float* __restrict__ out, float* __restrict__ stat_out, int M) {
    extern __shared__ float smem[];
    float* As_hi = smem + SM_AH;
    float* As_lo = smem + SM_AL;
    float* Ws_hi = smem + SM_WH;
    float* Ws_lo = smem + SM_WL;
    float* s_sc = smem + SM_SC;
    float* s_sh = smem + SM_SH;
    float* s_st = smem + SM_ST;

    const int tid = threadIdx.x;
    const int lane = tid & 31;
    const int wid = tid >> 5;
    const int row0 = blockIdx.x * 64;

    const int g = lane >> 2;      // groupID
    const int t = lane & 3;       // threadID_in_group
    const int arow = (wid & 3) * 16;
    const int nbase = (wid >> 2) * 64;

    if (tid < HID) {
        if (BN_IN) {
            float mu = stat_in[tid] * invN;
            float var = stat_in[HID + tid] * invN - mu * mu;
            float sv = gamma[tid] * rsqrtf(var + 1e-5f);
            s_sc[tid] = sv;
            s_sh[tid] = beta[tid] - sv * mu;
        } else {
            s_sc[tid] = 1.f;
            s_sh[tid] = 0.f;
        }
    }
    s_st[tid] = 0.f;  // stats accumulators (256 floats)

    float d[8][4];
#pragma unroll
    for (int i = 0; i < 8; i++)
#pragma unroll
        for (int j = 0; j < 4; j++) d[i][j] = 0.f;

#pragma unroll 1
    for (int h = 0; h < 2; h++) {
        if (h) __syncthreads();  // all warps done reading previous half
        // ---- stage W half: k_local 0..63, cols 0..127 (split hi/lo) ----
        for (int i = tid; i < 2048; i += 256) {
            int kl = i >> 5, c4 = i & 31;
            float4 wv = __ldg((const float4*)(W + (size_t)(h * 64 + kl) * HID) + c4);
            float4 hi, lo;
            hi.x = tf32_rna(wv.x); lo.x = tf32_rna(wv.x - hi.x);
            hi.y = tf32_rna(wv.y); lo.y = tf32_rna(wv.y - hi.y);
            hi.z = tf32_rna(wv.z); lo.z = tf32_rna(wv.z - hi.z);
            hi.w = tf32_rna(wv.w); lo.w = tf32_rna(wv.w - hi.w);
            *(float4*)&Ws_hi[kl * WP + c4 * 4] = hi;
            *(float4*)&Ws_lo[kl * WP + c4 * 4] = lo;
        }
        // ---- stage A half: rows 0..63, cols h*64..h*64+63, with input transform ----
        for (int i = tid; i < 1024; i += 256) {
            int r = i >> 4, c4 = i & 15;
            int gr = row0 + r;
            int gc4 = h * 16 + c4;
            float4 v = make_float4(0.f, 0.f, 0.f, 0.f);
            if (gr < M) {
                float4 zv = __ldg((const float4*)(A + (size_t)gr * HID) + gc4);
                float4 s4 = *(const float4*)&s_sc[gc4 * 4];
                float4 h4 = *(const float4*)&s_sh[gc4 * 4];
                v.x = fmaf(s4.x, zv.x, h4.x);
                v.y = fmaf(s4.y, zv.y, h4.y);
                v.z = fmaf(s4.z, zv.z, h4.z);
                v.w = fmaf(s4.w, zv.w, h4.w);
                if (RELU_IN) {
                    v.x = fmaxf(v.x, 0.f); v.y = fmaxf(v.y, 0.f);
                    v.z = fmaxf(v.z, 0.f); v.w = fmaxf(v.w, 0.f);
                }
                if (HAS_A2) {
                    float4 a2 = __ldg((const float4*)(A2 + (size_t)gr * HID) + gc4);
                    v.x += a2.x; v.y += a2.y; v.z += a2.z; v.w += a2.w;
                }
            }
            float4 hi, lo;
            hi.x = tf32_rna(v.x); lo.x = tf32_rna(v.x - hi.x);
            hi.y = tf32_rna(v.y); lo.y = tf32_rna(v.y - hi.y);
            hi.z = tf32_rna(v.z); lo.z = tf32_rna(v.z - hi.z);
            hi.w = tf32_rna(v.w); lo.w = tf32_rna(v.w - hi.w);
            *(float4*)&As_hi[r * AP + c4 * 4] = hi;
            *(float4*)&As_lo[r * AP + c4 * 4] = lo;
        }
        __syncthreads();

        // ---- mma mainloop over 8 k-steps ----
#pragma unroll
        for (int kk8 = 0; kk8 < 8; kk8++) {
            int ab = (arow + g) * AP + kk8 * 8 + t;
            unsigned ah0 = __float_as_uint(As_hi[ab]);
            unsigned ah1 = __float_as_uint(As_hi[ab + 8 * AP]);
            unsigned ah2 = __float_as_uint(As_hi[ab + 4]);
            unsigned ah3 = __float_as_uint(As_hi[ab + 8 * AP + 4]);
            unsigned al0 = __float_as_uint(As_lo[ab]);
            unsigned al1 = __float_as_uint(As_lo[ab + 8 * AP]);
            unsigned al2 = __float_as_uint(As_lo[ab + 4]);
            unsigned al3 = __float_as_uint(As_lo[ab + 8 * AP + 4]);
            int br0 = (kk8 * 8 + t) * WP;
            int br1 = (kk8 * 8 + t + 4) * WP;
#pragma unroll
            for (int nt = 0; nt < 8; nt++) {
                int bc = nbase + nt * 8 + g;
                unsigned bh0 = __float_as_uint(Ws_hi[br0 + bc]);
                unsigned bh1 = __float_as_uint(Ws_hi[br1 + bc]);
                unsigned bl0 = __float_as_uint(Ws_lo[br0 + bc]);
                unsigned bl1 = __float_as_uint(Ws_lo[br1 + bc]);
                mma_tf32(d[nt][0], d[nt][1], d[nt][2], d[nt][3],
                         ah0, ah1, ah2, ah3, bh0, bh1);
                mma_tf32(d[nt][0], d[nt][1], d[nt][2], d[nt][3],
                         ah0, ah1, ah2, ah3, bl0, bl1);
                mma_tf32(d[nt][0], d[nt][1], d[nt][2], d[nt][3],
                         al0, al1, al2, al3, bh0, bh1);
            }
        }
    }

    // ---- epilogue: D rows (g, g+8), cols (2t, 2t+1) per n-tile ----
    int gr0 = row0 + arow + g;
    int gr1 = gr0 + 8;
#pragma unroll
    for (int nt = 0; nt < 8; nt++) {
        int c0 = nbase + nt * 8 + 2 * t;
        float bv0 = __ldg(bias + c0);
        float bv1 = __ldg(bias + c0 + 1);
        float x0 = d[nt][0] + bv0, x1 = d[nt][1] + bv1;
        float x2 = d[nt][2] + bv0, x3 = d[nt][3] + bv1;
        if (RELU_OUT) {
            x0 = fmaxf(x0, 0.f); x1 = fmaxf(x1, 0.f);
            x2 = fmaxf(x2, 0.f); x3 = fmaxf(x3, 0.f);
        }
        if (gr0 < M) {
            *(float2*)(out + (size_t)gr0 * HID + c0) = make_float2(x0, x1);
            if (STATS) {
                atomicAdd(&s_st[c0], x0);
                atomicAdd(&s_st[c0 + 1], x1);
                atomicAdd(&s_st[128 + c0], x0 * x0);
                atomicAdd(&s_st[128 + c0 + 1], x1 * x1);
            }
        }
        if (gr1 < M) {
            *(float2*)(out + (size_t)gr1 * HID + c0) = make_float2(x2, x3);
            if (STATS) {
                atomicAdd(&s_st[c0], x2);
                atomicAdd(&s_st[c0 + 1], x3);
                atomicAdd(&s_st[128 + c0], x2 * x2);
                atomicAdd(&s_st[128 + c0 + 1], x3 * x3);
            }
        }
    }
    if (STATS) {
        __syncthreads();
        if (tid < 128) {
            atomicAdd(&stat_out[tid], s_st[tid]);
            atomicAdd(&stat_out[HID + tid], s_st[128 + tid]);
        }
    }
}

// ================= launcher =================
extern "C" void kernel_launch(void* const* d_in, const int* in_sizes, int n_in,
                              void* d_out, int out_size) {
    const float* x = (const float*)d_in[0];
    const int* ei = (const int*)d_in[1];   // int32 (JAX default, x64 disabled)
    const float* ea = (const float*)d_in[2];
    const float* W1 = (const float*)d_in[3];
    const float* b1 = (const float*)d_in[4];
    const float* g1 = (const float*)d_in[5];
    const float* be1 = (const float*)d_in[6];
    const float* W2 = (const float*)d_in[7];
    const float* b2 = (const float*)d_in[8];
    const float* bn_g = (const float*)d_in[9];
    const float* bn_b = (const float*)d_in[10];

    int M = in_sizes[0] / HID;
    int E = in_sizes[2] / HID;
    float* out = (float*)d_out;

    void *agg_p, *z_p, *t_p, *stats_p;
    cudaGetSymbolAddress(&agg_p, g_agg);
    cudaGetSymbolAddress(&z_p, g_z);
    cudaGetSymbolAddress(&t_p, g_t);
    cudaGetSymbolAddress(&stats_p, g_stats);
    float* stats = (float*)stats_p;

    cudaFuncSetAttribute(gemm_kernel<false, true, false, false, true>,
                         cudaFuncAttributeMaxDynamicSharedMemorySize, GEMM_SMEM);
    cudaFuncSetAttribute(gemm_kernel<true, true, false, false, true>,
                         cudaFuncAttributeMaxDynamicSharedMemorySize, GEMM_SMEM);
    cudaFuncSetAttribute(gemm_kernel<true, false, true, true, true>,
                         cudaFuncAttributeMaxDynamicSharedMemorySize, GEMM_SMEM);
    cudaFuncSetAttribute(gemm_kernel<true, false, true, true, false>,
                         cudaFuncAttributeMaxDynamicSharedMemorySize, GEMM_SMEM);

    const int* srcI = ei;
    const int* dstI = ei + E;
    int eb = (E + 255) / 256;
    int gb = (M + 63) / 64;
    int ab = (M * 32 + 255) / 256;
    float invN = 1.0f / (float)M;

    hist_kernel<<<eb, 256>>>(dstI, E);
    scan_kernel<<<1, 1024>>>(M, E);
    scatter_kernel<<<eb, 256>>>(dstI, E);

    for (int i = 0; i < 4; i++) {
        const float* zsrc = (i == 0) ? x : (const float*)z_p;
        float* stat_t = stats + (size_t)(2 * i) * 2 * HID;
        float* stat_z = stats + (size_t)(2 * i + 1) * 2 * HID;
        float* stat_z_prev = stats + (size_t)(2 * i - 1) * 2 * HID;

        if (i == 0)
            agg_kernel<false><<<ab, 256>>>(zsrc, ea, srcI, nullptr, nullptr, nullptr,
                                           (float*)agg_p, M, invN);
        else
            agg_kernel<true><<<ab, 256>>>(zsrc, ea, srcI, stat_z_prev,
                                          bn_g + (size_t)(i - 1) * HID,
                                          bn_b + (size_t)(i - 1) * HID,
                                          (float*)agg_p, M, invN);

        if (i == 0)
            gemm_kernel<false, true, false, false, true><<<gb, 256, GEMM_SMEM>>>(
                zsrc, (const float*)agg_p, nullptr, nullptr, nullptr, invN,
                W1, b1, (float*)t_p, stat_t, M);
        else
            gemm_kernel<true, true, false, false, true><<<gb, 256, GEMM_SMEM>>>(
                zsrc, (const float*)agg_p, stat_z_prev,
                bn_g + (size_t)(i - 1) * HID, bn_b + (size_t)(i - 1) * HID, invN,
                W1 + (size_t)i * HID * HID, b1 + (size_t)i * HID,
                (float*)t_p, stat_t, M);

        if (i < 3)
            gemm_kernel<true, false, true, true, true><<<gb, 256, GEMM_SMEM>>>(
                (const float*)t_p, nullptr, stat_t,
                g1 + (size_t)i * HID, be1 + (size_t)i * HID, invN,
                W2 + (size_t)i * HID * HID, b2 + (size_t)i * HID,
                (float*)z_p, stat_z, M);
        else
            gemm_kernel<true, false, true, true, false><<<gb, 256, GEMM_SMEM>>>(
                (const float*)t_p, nullptr, stat_t,
                g1 + (size_t)i * HID, be1 + (size_t)i * HID, invN,
                W2 + (size_t)i * HID * HID, b2 + (size_t)i * HID,
                out, nullptr, M);
    }
}

// round 9
// speedup vs baseline: 1.7272x; 1.7272x over previous
#include <cuda_runtime.h>
#include <cstdint>

#define HID 128
#define MAXN 50000
#define MAXE 640000

// ---------------- scratch (device globals; no allocation allowed) ----------------
__device__ __align__(256) float g_z[MAXN * HID];       // raw (pre-BN) layer output
__device__ __align__(256) float g_agg[MAXN * HID];     // BN(z)+sum relu(...) (GEMM1 input)
__device__ __align__(256) float g_t[MAXN * HID];       // post-GEMM1 pre-BN
__device__ __align__(256) float g_stats[8 * 2 * HID];  // per-layer [sum|sumsq] slots
__device__ int g_cnt[MAXN];       // histogram (re-zeroed by scan each call)
__device__ int g_cur[MAXN];       // scatter cursor (zeroed by scan each call)
__device__ int g_rowptr[MAXN + 1];
__device__ int g_elist[MAXE];

// ---------------- f32x2 helpers ----------------
__device__ __forceinline__ unsigned long long pk2(float a) {
    unsigned long long r;
    asm("mov.b64 %0, {%1, %1};" : "=l"(r) : "f"(a));
    return r;
}
__device__ __forceinline__ void fma2(unsigned long long& d, unsigned long long a, unsigned long long b) {
    asm("fma.rn.f32x2 %0, %1, %2, %0;" : "+l"(d) : "l"(a), "l"(b));
}
__device__ __forceinline__ float2 upk(unsigned long long v) {
    float2 r;
    asm("mov.b64 {%0, %1}, %2;" : "=f"(r.x), "=f"(r.y) : "l"(v));
    return r;
}

// ================= CSR build =================
__global__ void hist_kernel(const int* __restrict__ dst, int E) {
    int i = blockIdx.x * blockDim.x + threadIdx.x;
    if (i < E) atomicAdd(&g_cnt[dst[i]], 1);
}

// scan + zero cnt/cur/stats (keeps replays deterministic without extra memsets)
__global__ void __launch_bounds__(1024) scan_kernel(int N, int E) {
    __shared__ int part[1024];
    int tid = threadIdx.x;
    int chunk = (N + 1023) / 1024;
    int base = tid * chunk;
    int s = 0;
    for (int j = 0; j < chunk; j++) {
        int idx = base + j;
        if (idx < N) s += g_cnt[idx];
    }
    part[tid] = s;
    __syncthreads();
    for (int off = 1; off < 1024; off <<= 1) {
        int v = (tid >= off) ? part[tid - off] : 0;
        __syncthreads();
        part[tid] += v;
        __syncthreads();
    }
    int run = (tid == 0) ? 0 : part[tid - 1];
    for (int j = 0; j < chunk; j++) {
        int idx = base + j;
        if (idx < N) {
            g_rowptr[idx] = run;
            run += g_cnt[idx];
            g_cnt[idx] = 0;
            g_cur[idx] = 0;
        }
    }
    if (tid == 1023) g_rowptr[N] = E;
    g_stats[tid] = 0.f;
    g_stats[tid + 1024] = 0.f;
}

__global__ void scatter_kernel(const int* __restrict__ dst, int E) {
    int i = blockIdx.x * blockDim.x + threadIdx.x;
    if (i < E) {
        int d = dst[i];
        int p = atomicAdd(&g_cur[d], 1);
        g_elist[g_rowptr[d] + p] = i;
    }
}

// ================= aggregate: warp per node, writes BN(z[node]) + sum relu(...) =====
template <bool BN>
__global__ void __launch_bounds__(256) agg_kernel(
    const float* __restrict__ z, const float* __restrict__ ea,
    const int* __restrict__ srcI, const float* __restrict__ stat_in,
    const float* __restrict__ gamma, const float* __restrict__ beta,
    float* __restrict__ agg, int N, float invN) {
    __shared__ float s_sc[HID], s_sh[HID];
    if (BN) {
        if (threadIdx.x < HID) {
            int c = threadIdx.x;
            float mu = stat_in[c] * invN;
            float var = stat_in[HID + c] * invN - mu * mu;
            float sv = gamma[c] * rsqrtf(var + 1e-5f);
            s_sc[c] = sv;
            s_sh[c] = beta[c] - sv * mu;
        }
        __syncthreads();
    }
    int warp = (blockIdx.x * blockDim.x + threadIdx.x) >> 5;
    int lane = threadIdx.x & 31;
    if (warp >= N) return;

    float4 sc, sh;
    if (BN) {
        sc = *(const float4*)&s_sc[lane * 4];
        sh = *(const float4*)&s_sh[lane * 4];
    }

    int idx = g_rowptr[warp];
    const int end = g_rowptr[warp + 1];
    // self term: BN(z[node])
    float4 acc = __ldg((const float4*)(z + (size_t)warp * HID) + lane);
    if (BN) {
        acc.x = fmaf(sc.x, acc.x, sh.x);
        acc.y = fmaf(sc.y, acc.y, sh.y);
        acc.z = fmaf(sc.z, acc.z, sh.z);
        acc.w = fmaf(sc.w, acc.w, sh.w);
    }

#define EDGE_BODY(E_, S_)                                                     \
    {                                                                         \
        float4 zv = __ldg((const float4*)(z + (size_t)(S_) * HID) + lane);    \
        float4 av = __ldcs((const float4*)(ea + (size_t)(E_) * HID) + lane);  \
        if (BN) {                                                             \
            zv.x = fmaf(sc.x, zv.x, sh.x); zv.y = fmaf(sc.y, zv.y, sh.y);     \
            zv.z = fmaf(sc.z, zv.z, sh.z); zv.w = fmaf(sc.w, zv.w, sh.w);     \
        }                                                                     \
        acc.x += fmaxf(zv.x + av.x, 0.f);                                     \
        acc.y += fmaxf(zv.y + av.y, 0.f);                                     \
        acc.z += fmaxf(zv.z + av.z, 0.f);                                     \
        acc.w += fmaxf(zv.w + av.w, 0.f);                                     \
    }

    for (; idx + 4 <= end; idx += 4) {
        int e0 = __ldg(g_elist + idx);
        int e1 = __ldg(g_elist + idx + 1);
        int e2 = __ldg(g_elist + idx + 2);
        int e3 = __ldg(g_elist + idx + 3);
        int s0 = __ldg(srcI + e0);
        int s1 = __ldg(srcI + e1);
        int s2 = __ldg(srcI + e2);
        int s3 = __ldg(srcI + e3);
        EDGE_BODY(e0, s0) EDGE_BODY(e1, s1) EDGE_BODY(e2, s2) EDGE_BODY(e3, s3)
    }
    for (; idx < end; idx++) {
        int e0 = __ldg(g_elist + idx);
        int s0 = __ldg(srcI + e0);
        EDGE_BODY(e0, s0)
    }
#undef EDGE_BODY
    ((float4*)(agg + (size_t)warp * HID))[lane] = acc;  // every row written: no memset
}

// ================= fused GEMM (R4/R6 mapping: warp w rows w*8, lane cols lane*4) ====
static const int GEMM_SMEM = (HID * HID + 64 * 132 + 2 * HID) * 4;  // 100352 B

template <bool BN_IN, bool RELU_IN, bool RELU_OUT, bool STATS>
__global__ void __launch_bounds__(256) gemm_kernel(
    const float* __restrict__ A,
    const float* __restrict__ stat_in, const float* __restrict__ gamma,
    const float* __restrict__ beta, float invN,
    const float* __restrict__ W, const float* __restrict__ bias,
    float* __restrict__ out, float* __restrict__ stat_out, int M) {
    extern __shared__ float smem[];
    float* Ws = smem;                        // [128][128]
    float* As = smem + HID * HID;            // [64][132]
    float* s_sc = smem + HID * HID + 64 * 132;
    float* s_sh = s_sc + HID;

    const int tid = threadIdx.x;
    const int lane = tid & 31;
    const int wid = tid >> 5;
    const int row0 = blockIdx.x * 64;

    if (BN_IN && tid < HID) {
        float mu = stat_in[tid] * invN;
        float var = stat_in[HID + tid] * invN - mu * mu;
        float sv = gamma[tid] * rsqrtf(var + 1e-5f);
        s_sc[tid] = sv;
        s_sh[tid] = beta[tid] - sv * mu;
    }

    const float4* Wg = (const float4*)W;
    float4* Ws4 = (float4*)Ws;
#pragma unroll
    for (int i = 0; i < 16; i++) Ws4[tid + 256 * i] = __ldg(Wg + tid + 256 * i);
    __syncthreads();

    for (int i = tid; i < 64 * 32; i += 256) {
        int r = i >> 5, c4 = i & 31;
        int gr = row0 + r;
        float4 v = make_float4(0.f, 0.f, 0.f, 0.f);
        if (gr < M) {
            v = __ldg((const float4*)(A + (size_t)gr * HID) + c4);
            if (BN_IN) {
                float4 s4 = *(const float4*)&s_sc[c4 * 4];
                float4 h4 = *(const float4*)&s_sh[c4 * 4];
                v.x = fmaf(s4.x, v.x, h4.x);
                v.y = fmaf(s4.y, v.y, h4.y);
                v.z = fmaf(s4.z, v.z, h4.z);
                v.w = fmaf(s4.w, v.w, h4.w);
            }
            if (RELU_IN) {
                v.x = fmaxf(v.x, 0.f); v.y = fmaxf(v.y, 0.f);
                v.z = fmaxf(v.z, 0.f); v.w = fmaxf(v.w, 0.f);
            }
        }
        *(float4*)&As[r * 132 + c4 * 4] = v;
    }
    __syncthreads();

    unsigned long long acc[16];
#pragma unroll
    for (int i = 0; i < 16; i++) acc[i] = 0ull;

    const int arow = wid * 8;
#pragma unroll 2
    for (int kk = 0; kk < HID; kk += 4) {
        float ar[8][4];
#pragma unroll
        for (int r = 0; r < 8; r++)
            *(float4*)ar[r] = *(const float4*)&As[(arow + r) * 132 + kk];
#pragma unroll
        for (int j = 0; j < 4; j++) {
            ulonglong2 w = *(const ulonglong2*)&Ws[(kk + j) * HID + lane * 4];
#pragma unroll
            for (int r = 0; r < 8; r++) {
                unsigned long long pa = pk2(ar[r][j]);
                fma2(acc[r * 2 + 0], pa, w.x);
                fma2(acc[r * 2 + 1], pa, w.y);
            }
        }
    }

    float bb[4];
    *(float4*)bb = __ldg((const float4*)bias + lane);
    float csum[4], csq[4];
#pragma unroll
    for (int j = 0; j < 4; j++) { csum[j] = 0.f; csq[j] = 0.f; }

#pragma unroll
    for (int r = 0; r < 8; r++) {
        int gr = row0 + arow + r;
        if (gr < M) {
            float2 u0 = upk(acc[r * 2 + 0]);
            float2 u1 = upk(acc[r * 2 + 1]);
            float v[4] = {u0.x + bb[0], u0.y + bb[1], u1.x + bb[2], u1.y + bb[3]};
            if (RELU_OUT) {
#pragma unroll
                for (int j = 0; j < 4; j++) v[j] = fmaxf(v[j], 0.f);
            }
            *(float4*)(out + (size_t)gr * HID + lane * 4) = make_float4(v[0], v[1], v[2], v[3]);
            if (STATS) {
#pragma unroll
                for (int j = 0; j < 4; j++) { csum[j] += v[j]; csq[j] += v[j] * v[j]; }
            }
        }
    }

    if (STATS) {
        float* red = As;  // reuse: 8 warps x 256 floats
        __syncthreads();
#pragma unroll
        for (int j = 0; j < 4; j++) {
            red[wid * 256 + lane * 4 + j] = csum[j];
            red[wid * 256 + 128 + lane * 4 + j] = csq[j];
        }
        __syncthreads();
#pragma unroll
        for (int s = 4; s > 0; s >>= 1) {
            if (wid < s) {
                for (int i = lane; i < 256; i += 32)
                    red[wid * 256 + i] += red[(wid + s) * 256 + i];
            }
            __syncthreads();
        }
        if (wid == 0) {
#pragma unroll
            for (int j = 0; j < 4; j++) {
                atomicAdd(&stat_out[lane * 4 + j], red[lane * 4 + j]);
                atomicAdd(&stat_out[HID + lane * 4 + j], red[128 + lane * 4 + j]);
            }
        }
    }
}

// ================= launcher =================
extern "C" void kernel_launch(void* const* d_in, const int* in_sizes, int n_in,
                              void* d_out, int out_size) {
    const float* x = (const float*)d_in[0];
    const int* ei = (const int*)d_in[1];   // int32 (JAX default, x64 disabled)
    const float* ea = (const float*)d_in[2];
    const float* W1 = (const float*)d_in[3];
    const float* b1 = (const float*)d_in[4];
    const float* g1 = (const float*)d_in[5];
    const float* be1 = (const float*)d_in[6];
    const float* W2 = (const float*)d_in[7];
    const float* b2 = (const float*)d_in[8];
    const float* bn_g = (const float*)d_in[9];
    const float* bn_b = (const float*)d_in[10];

    int M = in_sizes[0] / HID;
    int E = in_sizes[2] / HID;
    float* out = (float*)d_out;

    void *agg_p, *z_p, *t_p, *stats_p;
    cudaGetSymbolAddress(&agg_p, g_agg);
    cudaGetSymbolAddress(&z_p, g_z);
    cudaGetSymbolAddress(&t_p, g_t);
    cudaGetSymbolAddress(&stats_p, g_stats);
    float* stats = (float*)stats_p;

    cudaFuncSetAttribute(gemm_kernel<false, false, false, true>,
                         cudaFuncAttributeMaxDynamicSharedMemorySize, GEMM_SMEM);
    cudaFuncSetAttribute(gemm_kernel<true, true, true, true>,
                         cudaFuncAttributeMaxDynamicSharedMemorySize, GEMM_SMEM);
    cudaFuncSetAttribute(gemm_kernel<true, true, true, false>,
                         cudaFuncAttributeMaxDynamicSharedMemorySize, GEMM_SMEM);

    const int* srcI = ei;
    const int* dstI = ei + E;
    int eb = (E + 255) / 256;
    int gb = (M + 63) / 64;
    int ab = (M * 32 + 255) / 256;  // warp per node
    float invN = 1.0f / (float)M;

    // CSR build (scan also zeroes stats/cnt/cur for graph replays)
    hist_kernel<<<eb, 256>>>(dstI, E);
    scan_kernel<<<1, 1024>>>(M, E);
    scatter_kernel<<<eb, 256>>>(dstI, E);

    for (int i = 0; i < 4; i++) {
        const float* zsrc = (i == 0) ? x : (const float*)z_p;
        float* stat_t = stats + (size_t)(2 * i) * 2 * HID;
        float* stat_z = stats + (size_t)(2 * i + 1) * 2 * HID;
        float* stat_z_prev = stats + (size_t)(2 * i - 1) * 2 * HID;

        // aggregate includes the self/residual term: GEMM1 input fully formed here
        if (i == 0)
            agg_kernel<false><<<ab, 256>>>(zsrc, ea, srcI, nullptr, nullptr, nullptr,
                                           (float*)agg_p, M, invN);
        else
            agg_kernel<true><<<ab, 256>>>(zsrc, ea, srcI, stat_z_prev,
                                          bn_g + (size_t)(i - 1) * HID,
                                          bn_b + (size_t)(i - 1) * HID,
                                          (float*)agg_p, M, invN);

        // GEMM1: raw stage of agg (no transform)
        gemm_kernel<false, false, false, true><<<gb, 256, GEMM_SMEM>>>(
            (const float*)agg_p, nullptr, nullptr, nullptr, invN,
            W1 + (size_t)i * HID * HID, b1 + (size_t)i * HID,
            (float*)t_p, stat_t, M);

        // GEMM2: BN(t)+ReLU in, ReLU out
        if (i < 3)
            gemm_kernel<true, true, true, true><<<gb, 256, GEMM_SMEM>>>(
                (const float*)t_p, stat_t,
                g1 + (size_t)i * HID, be1 + (size_t)i * HID, invN,
                W2 + (size_t)i * HID * HID, b2 + (size_t)i * HID,
                (float*)z_p, stat_z, M);
        else
            gemm_kernel<true, true, true, false><<<gb, 256, GEMM_SMEM>>>(
                (const float*)t_p, stat_t,
                g1 + (size_t)i * HID, be1 + (size_t)i * HID, invN,
                W2 + (size_t)i * HID * HID, b2 + (size_t)i * HID,
                out, nullptr, M);
    }
}